// round 17
// baseline (speedup 1.0000x reference)
#include <cuda_runtime.h>
#include <cuda_fp16.h>
#include <cstdint>

// Problem-size caps (fixed by the dataset)
#define MAXN 100000
#define MAXE 1600000
#define DFEAT 48
#define NH2   24          // half2 per node row
#define KITER 10
#define ALPHA 0.1f

// ---------------- scratch (static device memory; no allocations) -------------
__device__ int     g_is64;
__device__ int     g_deg[MAXN];
__device__ int     g_off[MAXN + 1];
__device__ int     g_bsums[256];
__device__ int     g_slot[MAXE];
__device__ int2    g_edge[MAXE];                    // (col, raw-w bits), row-sorted
__device__ __half2 g_xh[(size_t)MAXN * NH2];        // x in fp16
__device__ __half2 g_hh0[(size_t)MAXN * NH2];       // ping
__device__ __half2 g_hh1[(size_t)MAXN * NH2];       // pong

// ---------------- precompute kernels ----------------------------------------

// Detect int64 vs int32 edge_index: int64 (values < 2^31) has every odd 32-bit
// word zero; int32 data has random indices there.
__global__ void k_detect(const int* __restrict__ ei32, int E) {
    __shared__ int any;
    if (threadIdx.x == 0) any = 0;
    __syncthreads();
    int nchk = 1024; if (nchk > E) nchk = E;
    for (int i = threadIdx.x; i < nchk; i += blockDim.x)
        if (ei32[2 * i + 1] != 0) any = 1;
    __syncthreads();
    if (threadIdx.x == 0) g_is64 = (any == 0) ? 1 : 0;
}

__global__ void k_zero(int* deg, int n) {
    int i = blockIdx.x * blockDim.x + threadIdx.x;
    if (i < n) deg[i] = 0;
}

// x (fp32) -> half2
__global__ void k_xhalf(const float2* __restrict__ x2, __half2* __restrict__ xh, int n2) {
    int i = blockIdx.x * blockDim.x + threadIdx.x;
    if (i < n2) xh[i] = __float22half2_rn(x2[i]);
}

// Degree count + per-row slot per edge. 4 edges/thread (measured-best config).
__global__ void k_narrow(const void* __restrict__ ei,
                         int* __restrict__ deg, int* __restrict__ slot,
                         int E, int N) {
    int base = (blockIdx.x * blockDim.x + threadIdx.x) * 4;
    if (base >= E) return;
    int r[4];
    if (g_is64) {
        const longlong2* p = (const longlong2*)ei;
        longlong2 a = __ldg(&p[(base >> 1)]);
        longlong2 b = __ldg(&p[(base >> 1) + 1]);
        r[0] = (int)a.x; r[1] = (int)a.y; r[2] = (int)b.x; r[3] = (int)b.y;
    } else {
        const int4* p = (const int4*)ei;
        int4 a = __ldg(&p[base >> 2]);
        r[0] = a.x; r[1] = a.y; r[2] = a.z; r[3] = a.w;
    }
#pragma unroll
    for (int j = 0; j < 4; j++) {
        int e = base + j;
        if (e >= E) break;
        int rr = r[j];
        if (rr < 0) rr = 0; if (rr >= N) rr = N - 1;   // crash-proofing only
        slot[e] = atomicAdd(&deg[rr], 1);
    }
}

// 3-phase exclusive scan of deg -> off
__global__ void k_scan1(const int* __restrict__ deg, int* __restrict__ off,
                        int* __restrict__ bsums, int n) {
    __shared__ int sh[1024];
    int i = blockIdx.x * 1024 + threadIdx.x;
    int v = (i < n) ? deg[i] : 0;
    sh[threadIdx.x] = v;
    __syncthreads();
    for (int d = 1; d < 1024; d <<= 1) {
        int t = 0;
        if (threadIdx.x >= d) t = sh[threadIdx.x - d];
        __syncthreads();
        if (threadIdx.x >= d) sh[threadIdx.x] += t;
        __syncthreads();
    }
    if (i < n) off[i] = sh[threadIdx.x] - v;
    if (threadIdx.x == 1023) bsums[blockIdx.x] = sh[1023];
}

__global__ void k_scan2(int* bsums, int nb) {
    if (threadIdx.x == 0 && blockIdx.x == 0) {
        int acc = 0;
        for (int i = 0; i < nb; i++) { int t = bsums[i]; bsums[i] = acc; acc += t; }
    }
}

__global__ void k_scan3(int* __restrict__ off, const int* __restrict__ bsums,
                        int n, int total) {
    int i = blockIdx.x * 1024 + threadIdx.x;
    if (i < n) off[i] += bsums[blockIdx.x];
    if (i == 0) off[n] = total;
}

// Counting-sort scatter using precomputed slots (no atomics): (col, raw w).
// 4 edges/thread, vector loads for MLP.
__global__ void k_scatter(const void* __restrict__ ei,
                          const int* __restrict__ slot,
                          const float* __restrict__ w,
                          const int* __restrict__ off, int2* __restrict__ ed,
                          int E, int N) {
    int base = (blockIdx.x * blockDim.x + threadIdx.x) * 4;
    if (base >= E) return;
    if (base + 4 <= E) {
        int r[4], c[4];
        if (g_is64) {
            const longlong2* p = (const longlong2*)ei;
            longlong2 a = __ldg(&p[base >> 1]);
            longlong2 b = __ldg(&p[(base >> 1) + 1]);
            r[0] = (int)a.x; r[1] = (int)a.y; r[2] = (int)b.x; r[3] = (int)b.y;
            longlong2 cA = __ldg(&p[(E + base) >> 1]);
            longlong2 cB = __ldg(&p[((E + base) >> 1) + 1]);
            c[0] = (int)cA.x; c[1] = (int)cA.y; c[2] = (int)cB.x; c[3] = (int)cB.y;
        } else {
            const int4* p = (const int4*)ei;
            int4 a = __ldg(&p[base >> 2]);
            int4 cc = __ldg(&p[(E + base) >> 2]);
            r[0] = a.x; r[1] = a.y; r[2] = a.z; r[3] = a.w;
            c[0] = cc.x; c[1] = cc.y; c[2] = cc.z; c[3] = cc.w;
        }
        float4 wv = __ldg((const float4*)(w + base));
        float wa[4] = {wv.x, wv.y, wv.z, wv.w};
        int4 sl = __ldg((const int4*)(slot + base));
        int sa[4] = {sl.x, sl.y, sl.z, sl.w};
#pragma unroll
        for (int j = 0; j < 4; j++) {
            int rr = r[j], cc2 = c[j];
            if (rr < 0) rr = 0; if (rr >= N) rr = N - 1;
            if (cc2 < 0) cc2 = 0; if (cc2 >= N) cc2 = N - 1;
            int p2 = __ldg(&off[rr]) + sa[j];
            ed[p2] = make_int2(cc2, __float_as_int(wa[j]));
        }
    } else {
        for (int e = base; e < E; e++) {
            int rr = g_is64 ? (int)((const long long*)ei)[e] : ((const int*)ei)[e];
            int cc2 = g_is64 ? (int)((const long long*)ei)[(size_t)E + e]
                             : ((const int*)ei)[E + e];
            if (rr < 0) rr = 0; if (rr >= N) rr = N - 1;
            if (cc2 < 0) cc2 = 0; if (cc2 >= N) cc2 = N - 1;
            ed[off[rr] + slot[e]] = make_int2(cc2, __float_as_int(w[e]));
        }
    }
}

// ---------------- propagation mainloop ---------------------------------------
// ONE WARP PER NODE. 4 groups x 8 lanes process 4 CONSECUTIVE edges of the
// same row per iteration: payload 4x int2 = one 32B window (~1 wavefront vs 4),
// zero intra-warp degree divergence. Lane l of a group owns half2 chunks
// {l, l+8, l+16}. Cross-group reduction via 2 SHFL rounds; lanes 0-7 write.
// Normalization folded into epilogue: 0.9/(sum_w + 1e-10).
template<bool FINAL>
__global__ void __launch_bounds__(256)
k_propw(const __half2* __restrict__ hin,
        const __half2* __restrict__ xh, const float2* __restrict__ x2,
        __half2* __restrict__ hout, float2* __restrict__ fout,
        const int* __restrict__ off, const int2* __restrict__ ed, int n) {
    int node = (blockIdx.x * blockDim.x + threadIdx.x) >> 5;
    if (node >= n) return;
    int lane = threadIdx.x & 31;
    int grp  = lane >> 3;          // 0..3: which edge of the 4-batch
    int l    = lane & 7;           // chunk position within row

    int s = __ldg(&off[node]);
    int e = __ldg(&off[node + 1]);

    float a0x = 0.f, a0y = 0.f, a1x = 0.f, a1y = 0.f, a2x = 0.f, a2y = 0.f;
    float ws = 0.f;
    for (int idx = s + grp; idx < e; idx += 4) {
        int2 t = __ldg(&ed[idx]);                 // 4 consecutive int2 per warp
        float ww = __int_as_float(t.y);
        ws += ww;
        const __half2* hp = hin + t.x * NH2 + l;
        float2 v0 = __half22float2(__ldg(hp));
        float2 v1 = __half22float2(__ldg(hp + 8));
        float2 v2 = __half22float2(__ldg(hp + 16));
        a0x = fmaf(ww, v0.x, a0x);  a0y = fmaf(ww, v0.y, a0y);
        a1x = fmaf(ww, v1.x, a1x);  a1y = fmaf(ww, v1.y, a1y);
        a2x = fmaf(ww, v2.x, a2x);  a2y = fmaf(ww, v2.y, a2y);
    }

    // reduce the 4 groups down to lanes 0-7
#pragma unroll
    for (int d = 16; d >= 8; d >>= 1) {
        a0x += __shfl_down_sync(0xffffffffu, a0x, d);
        a0y += __shfl_down_sync(0xffffffffu, a0y, d);
        a1x += __shfl_down_sync(0xffffffffu, a1x, d);
        a1y += __shfl_down_sync(0xffffffffu, a1y, d);
        a2x += __shfl_down_sync(0xffffffffu, a2x, d);
        a2y += __shfl_down_sync(0xffffffffu, a2y, d);
        ws  += __shfl_down_sync(0xffffffffu, ws,  d);
    }
    if (lane >= 8) return;

    float sc = (1.0f - ALPHA) / (ws + 1e-10f);

    int o = node * NH2 + l;
    float2 xv0, xv1, xv2;
    if (FINAL) {
        xv0 = __ldg(x2 + o); xv1 = __ldg(x2 + o + 8); xv2 = __ldg(x2 + o + 16);
    } else {
        xv0 = __half22float2(__ldg(xh + o));
        xv1 = __half22float2(__ldg(xh + o + 8));
        xv2 = __half22float2(__ldg(xh + o + 16));
    }
    float2 r0 = make_float2(fmaf(sc, a0x, ALPHA * xv0.x), fmaf(sc, a0y, ALPHA * xv0.y));
    float2 r1 = make_float2(fmaf(sc, a1x, ALPHA * xv1.x), fmaf(sc, a1y, ALPHA * xv1.y));
    float2 r2 = make_float2(fmaf(sc, a2x, ALPHA * xv2.x), fmaf(sc, a2y, ALPHA * xv2.y));

    if (FINAL) {
        fout[o] = r0; fout[o + 8] = r1; fout[o + 16] = r2;
    } else {
        hout[o]      = __float22half2_rn(r0);
        hout[o + 8]  = __float22half2_rn(r1);
        hout[o + 16] = __float22half2_rn(r2);
    }
}

// ---------------- launcher ----------------------------------------------------
extern "C" void kernel_launch(void* const* d_in, const int* in_sizes, int n_in,
                              void* d_out, int out_size) {
    const float* x  = (const float*)d_in[0];
    const void*  ei = d_in[1];
    const float* ew = (const float*)d_in[2];

    int N = in_sizes[0] / DFEAT;
    int E = in_sizes[2];
    if (N > MAXN) N = MAXN;
    if (E > MAXE) E = MAXE;

    int *deg, *off, *bsums, *slot;
    int2 *edge; __half2 *xh, *hh0, *hh1;
    cudaGetSymbolAddress((void**)&deg,   g_deg);
    cudaGetSymbolAddress((void**)&off,   g_off);
    cudaGetSymbolAddress((void**)&bsums, g_bsums);
    cudaGetSymbolAddress((void**)&slot,  g_slot);
    cudaGetSymbolAddress((void**)&edge,  g_edge);
    cudaGetSymbolAddress((void**)&xh,    g_xh);
    cudaGetSymbolAddress((void**)&hh0,   g_hh0);
    cudaGetSymbolAddress((void**)&hh1,   g_hh1);

    const float2* x2 = (const float2*)x;
    int nb  = (N + 1023) / 1024;
    int nh2 = N * NH2;

    k_detect<<<1, 256>>>((const int*)ei, E);
    k_zero<<<(N + 255) / 256, 256>>>(deg, N);
    k_xhalf<<<(nh2 + 255) / 256, 256>>>(x2, xh, nh2);
    k_narrow<<<((E + 3) / 4 + 255) / 256, 256>>>(ei, deg, slot, E, N);
    k_scan1<<<nb, 1024>>>(deg, off, bsums, N);
    k_scan2<<<1, 32>>>(bsums, nb);
    k_scan3<<<nb, 1024>>>(off, bsums, N, E);
    k_scatter<<<((E + 3) / 4 + 255) / 256, 256>>>(ei, slot, ew, off, edge, E, N);

    int pblocks = (N * 32 + 255) / 256;       // one warp per node
    const __half2* src = xh;
    for (int k = 0; k < KITER; k++) {
        if (k == KITER - 1) {
            k_propw<true><<<pblocks, 256>>>(src, xh, x2, nullptr, (float2*)d_out,
                                            off, edge, N);
        } else {
            __half2* dst = ((k & 1) == 0) ? hh0 : hh1;
            k_propw<false><<<pblocks, 256>>>(src, xh, x2, dst, nullptr,
                                             off, edge, N);
            src = dst;
        }
    }
}